// round 11
// baseline (speedup 1.0000x reference)
#include <cuda_runtime.h>
#include <cuda_fp16.h>
#include <math.h>

// Persistent device scratch (no allocation allowed in kernel_launch).
__device__ __half g_score_h[100032];   // fp16 score table (padded)

#define NS_BLOCKS 148
#define NS_THREADS 512

// ---------------------------------------------------------------------------
// Kernel 1: persistent node-score kernel (148 blocks, no wave tail).
// Coalesced SMEM staging of stride-7 rows; MLP with layer 3 folded into the
// layer-2 loop. Master node: setup pins it at node 0; serial fallback scan
// keeps correctness for arbitrary inputs (never taken on bench data).
// ---------------------------------------------------------------------------
__global__ void __launch_bounds__(NS_THREADS, 1)
node_score_kernel(const float* __restrict__ x_t,
                  const float* __restrict__ x_t_dt,
                  const float* __restrict__ W1,
                  const float* __restrict__ b1,
                  const float* __restrict__ W2,
                  const float* __restrict__ b2,
                  const float* __restrict__ W3,
                  const float* __restrict__ b3,
                  int n_nodes) {
    __shared__ float sW1[96];
    __shared__ float sb1[32];
    __shared__ __align__(16) float sW2[1024];
    __shared__ float sb2[32];
    __shared__ float sW3[32];
    __shared__ float sb3;
    __shared__ float smx, smy, smz;
    __shared__ __align__(16) float sx[NS_THREADS * 7];
    __shared__ __align__(16) float sxd[NS_THREADS * 7];

    int t = threadIdx.x;

    for (int k = t; k < 96; k += NS_THREADS) sW1[k] = W1[k];
    for (int k = t; k < 1024; k += NS_THREADS) sW2[k] = W2[k];
    if (t < 32) {
        sb1[t] = b1[t];
        sb2[t] = b2[t];
        sW3[t] = W3[t];
    }
    if (t == 0) {
        sb3 = b3[0];
        if (__ldg(&x_t[0]) == 1.0f) {           // fast path: master is node 0
            smx = __ldg(&x_t[1]);
            smy = __ldg(&x_t[2]);
            smz = __ldg(&x_t[3]);
        } else {                                 // fallback (never taken)
            for (int i = 1; i < n_nodes; i++) {
                if (__ldg(&x_t[(size_t)i * 7]) == 1.0f) {
                    smx = __ldg(&x_t[(size_t)i * 7 + 1]);
                    smy = __ldg(&x_t[(size_t)i * 7 + 2]);
                    smz = __ldg(&x_t[(size_t)i * 7 + 3]);
                    break;
                }
            }
        }
    }

    int npb = (n_nodes + NS_BLOCKS - 1) / NS_BLOCKS;
    int node_beg = blockIdx.x * npb;
    int node_end = min(node_beg + npb, n_nodes);

    for (int base = node_beg; base < node_end; base += NS_THREADS) {
        int nrows = min(NS_THREADS, node_end - base);
        int nflt = nrows * 7;
        const float* xr  = x_t    + (size_t)base * 7;
        const float* xdr = x_t_dt + (size_t)base * 7;
        for (int k = t; k < nflt; k += NS_THREADS) {
            sx[k]  = xr[k];
            sxd[k] = xdr[k];
        }
        __syncthreads();

        if (t < nrows) {
            float px = sx[t * 7 + 1];
            float py = sx[t * 7 + 2];
            float pz = sx[t * 7 + 3];
            float dx = sxd[t * 7 + 1] - px;
            float dy = sxd[t * 7 + 2] - py;
            float dz = sxd[t * 7 + 3] - pz;

            float dn = sqrtf(dx * dx + dy * dy + dz * dz);  // velocity_score
            float inv_dn = 1.0f / fmaxf(dn, 1e-12f);        // dt = 1
            float vx = dx * inv_dn, vy = dy * inv_dn, vz = dz * inv_dn;

            float rx = px - smx, ry = py - smy, rz = pz - smz;
            float rn = sqrtf(rx * rx + ry * ry + rz * rz);
            float dist = rn + 1e-6f;
            float na = fmaxf(rn, 1e-6f);
            float nb = fmaxf(sqrtf(vx * vx + vy * vy + vz * vz), 1e-6f);
            float dir_score = (rx * vx + ry * vy + rz * vz) / (na * nb);

            float a0 = 1.0f / dist;
            float a1 = dir_score;
            float a2 = dn;

            float h[32];
#pragma unroll
            for (int j = 0; j < 32; j++) {
                float s = fmaf(a2, sW1[j * 3 + 2],
                         fmaf(a1, sW1[j * 3 + 1],
                         fmaf(a0, sW1[j * 3 + 0], sb1[j])));
                h[j] = fmaxf(s, 0.0f);
            }

            const float4* w2v = reinterpret_cast<const float4*>(sW2);
            float s3 = sb3;
#pragma unroll
            for (int j = 0; j < 32; j++) {
                float s = sb2[j];
#pragma unroll
                for (int k4 = 0; k4 < 8; k4++) {
                    float4 w = w2v[j * 8 + k4];
                    s = fmaf(h[k4 * 4 + 0], w.x, s);
                    s = fmaf(h[k4 * 4 + 1], w.y, s);
                    s = fmaf(h[k4 * 4 + 2], w.z, s);
                    s = fmaf(h[k4 * 4 + 3], w.w, s);
                }
                s3 = fmaf(fmaxf(s, 0.0f), sW3[j], s3);
            }
            float sig = 1.0f / (1.0f + __expf(-s3));
            g_score_h[base + t] = __float2half(sig);
        }
        __syncthreads();
    }
}

// ---------------------------------------------------------------------------
// Kernel 2: half-table gather, 2 blocks per SM (64 warps/SM for latency
// hiding). Even blocks hold table[0..nh), odd blocks table[nh..2nh). Every
// block scans all edge indices; lookups/stores are predicated on ownership,
// so each output element is written by exactly one block. L2 merges the two
// halves' partial-sector writes before writeback.
// ---------------------------------------------------------------------------
#define G_THREADS 1024
__global__ void __launch_bounds__(G_THREADS, 2)
gather_kernel(const int* __restrict__ tgt,
              float* __restrict__ out,
              int n_edges, int nh) {
    extern __shared__ __align__(16) __half stab[];

    int half = blockIdx.x & 1;
    int base = half * nh;

    // Copy this half of the table (nh fp16 = nh/8 uint4, both 16B aligned).
    int n8 = nh >> 3;
    const uint4* src = reinterpret_cast<const uint4*>(g_score_h + base);
    uint4* dst = reinterpret_cast<uint4*>(stab);
    for (int k = threadIdx.x; k < n8; k += G_THREADS) dst[k] = src[k];
    __syncthreads();

    int n4 = n_edges >> 2;
    int nhalfblocks = gridDim.x >> 1;          // blocks per half (=148)
    int stride = nhalfblocks * G_THREADS;
    const int4* tv = reinterpret_cast<const int4*>(tgt);

    int j = (blockIdx.x >> 1) * G_THREADS + threadIdx.x;
    for (; j < n4; j += stride) {
        int4 a = tv[j];
        unsigned r0 = (unsigned)(a.x - base);
        unsigned r1 = (unsigned)(a.y - base);
        unsigned r2 = (unsigned)(a.z - base);
        unsigned r3 = (unsigned)(a.w - base);
        // Predicated lookups + scattered component stores (owned lanes only).
        if (r0 < (unsigned)nh) out[4 * j + 0] = __half2float(stab[r0]);
        if (r1 < (unsigned)nh) out[4 * j + 1] = __half2float(stab[r1]);
        if (r2 < (unsigned)nh) out[4 * j + 2] = __half2float(stab[r2]);
        if (r3 < (unsigned)nh) out[4 * j + 3] = __half2float(stab[r3]);
    }

    // Tail (n_edges % 4): one thread per half, ownership-predicated.
    if (blockIdx.x < 2 && threadIdx.x == 0) {
        for (int e = n4 << 2; e < n_edges; e++) {
            unsigned r = (unsigned)(tgt[e] - base);
            if (r < (unsigned)nh) out[e] = __half2float(stab[r]);
        }
    }
}

extern "C" void kernel_launch(void* const* d_in, const int* in_sizes, int n_in,
                              void* d_out, int out_size) {
    const float* x_t    = (const float*)d_in[0];
    const float* x_t_dt = (const float*)d_in[1];
    const int*   edge_index = (const int*)d_in[2];   // int32 (JAX x64 off)
    const float* W1 = (const float*)d_in[3];
    const float* b1 = (const float*)d_in[4];
    const float* W2 = (const float*)d_in[5];
    const float* b2 = (const float*)d_in[6];
    const float* W3 = (const float*)d_in[7];
    const float* b3 = (const float*)d_in[8];
    float* out = (float*)d_out;

    int n_nodes = in_sizes[0] / 7;
    int n_edges = in_sizes[2] / 2;
    const int* tgt = edge_index + n_edges;  // row 1 of (2, E)

    // Kernel 1: persistent node scores.
    node_score_kernel<<<NS_BLOCKS, NS_THREADS>>>(
        x_t, x_t_dt, W1, b1, W2, b2, W3, b3, n_nodes);

    // Kernel 2: half-table gather, 2 blocks/SM.
    // nh: half size, multiple of 16 halves (16B alignment for the copy).
    int nh = ((n_nodes + 1) / 2 + 15) & ~15;        // 50000 for n=100000
    size_t smem = (size_t)nh * sizeof(__half) + 16; // ~100KB
    cudaFuncSetAttribute(gather_kernel,
                         cudaFuncAttributeMaxDynamicSharedMemorySize,
                         (int)smem);
    gather_kernel<<<2 * 148, G_THREADS, smem>>>(tgt, out, n_edges, nh);
}

// round 12
// speedup vs baseline: 1.0667x; 1.0667x over previous
#include <cuda_runtime.h>
#include <cuda_fp16.h>
#include <math.h>

// Persistent device scratch (no allocation allowed in kernel_launch).
__device__ __half g_score_h[100032];   // fp16 score table (padded)
__device__ int    g_gen   = 0;         // barrier generation (monotonic, never reset)
__device__ int    g_count = 0;         // barrier arrival counter (reset by releaser)

#define NB 148
#define NT 1024

// ---------------------------------------------------------------------------
// Fused persistent kernel (148 blocks = 1/SM, all resident in wave 1).
//
// Phase 1: node scores. Each block owns <=676 nodes (single 1024-row chunk):
//          coalesced SMEM staging of the stride-7 rows, features, MLP
//          3->32->32->1 with layer 3 folded into the layer-2 loop, sigmoid,
//          fp16 store to the global table.
// Barrier: sense-reversing (gen counter monotonic; count reset BEFORE the
//          gen flip, spinners wait on gen) -> no reset/spin race, safe
//          across graph replays.
// Phase 2: gather. Warps 0-7 copy the 200KB table into SMEM while warps
//          8-31 process the first n4/8 edge groups L2-direct; then all
//          warps drain the rest from SMEM (int4 load -> 4x LDS.U16 ->
//          float4 store).
// ---------------------------------------------------------------------------
__global__ void __launch_bounds__(NT, 1)
fused_kernel(const float* __restrict__ x_t,
             const float* __restrict__ x_t_dt,
             const float* __restrict__ W1,
             const float* __restrict__ b1,
             const float* __restrict__ W2,
             const float* __restrict__ b2,
             const float* __restrict__ W3,
             const float* __restrict__ b3,
             const int* __restrict__ tgt,
             float* __restrict__ out,
             int n_nodes, int n_edges) {
    extern __shared__ __align__(16) char dsm[];
    float*  sx   = reinterpret_cast<float*>(dsm);        // phase-1 staging
    float*  sxd  = sx + NT * 7;
    __half* stab = reinterpret_cast<__half*>(dsm);       // phase-2 table

    __shared__ float sW1[96];
    __shared__ float sb1[32];
    __shared__ __align__(16) float sW2[1024];
    __shared__ float sb2[32];
    __shared__ float sW3[32];
    __shared__ float sb3;
    __shared__ float smx, smy, smz;

    int t = threadIdx.x;

    // ---- weights (once) ----
    for (int k = t; k < 96; k += NT) sW1[k] = W1[k];
    for (int k = t; k < 1024; k += NT) sW2[k] = W2[k];
    if (t < 32) {
        sb1[t] = b1[t];
        sb2[t] = b2[t];
        sW3[t] = W3[t];
    }
    if (t == 0) {
        sb3 = b3[0];
        // Master node: setup pins it at node 0; fallback scan keeps
        // correctness for arbitrary inputs (never taken on bench data).
        if (__ldg(&x_t[0]) == 1.0f) {
            smx = __ldg(&x_t[1]);
            smy = __ldg(&x_t[2]);
            smz = __ldg(&x_t[3]);
        } else {
            for (int i = 1; i < n_nodes; i++) {
                if (__ldg(&x_t[(size_t)i * 7]) == 1.0f) {
                    smx = __ldg(&x_t[(size_t)i * 7 + 1]);
                    smy = __ldg(&x_t[(size_t)i * 7 + 2]);
                    smz = __ldg(&x_t[(size_t)i * 7 + 3]);
                    break;
                }
            }
        }
    }

    // ---- Phase 1: node scores for this block's range ----
    int npb = (n_nodes + NB - 1) / NB;                 // <= NT by construction
    int node_beg = blockIdx.x * npb;
    int node_end = min(node_beg + npb, n_nodes);

    for (int base = node_beg; base < node_end; base += NT) {
        int nrows = min(NT, node_end - base);
        int nflt = nrows * 7;
        const float* xr  = x_t    + (size_t)base * 7;
        const float* xdr = x_t_dt + (size_t)base * 7;
        for (int k = t; k < nflt; k += NT) {
            sx[k]  = xr[k];
            sxd[k] = xdr[k];
        }
        __syncthreads();

        if (t < nrows) {
            float px = sx[t * 7 + 1];
            float py = sx[t * 7 + 2];
            float pz = sx[t * 7 + 3];
            float dx = sxd[t * 7 + 1] - px;
            float dy = sxd[t * 7 + 2] - py;
            float dz = sxd[t * 7 + 3] - pz;

            float dn = sqrtf(dx * dx + dy * dy + dz * dz);  // velocity_score
            float inv_dn = 1.0f / fmaxf(dn, 1e-12f);        // dt = 1
            float vx = dx * inv_dn, vy = dy * inv_dn, vz = dz * inv_dn;

            float rx = px - smx, ry = py - smy, rz = pz - smz;
            float rn = sqrtf(rx * rx + ry * ry + rz * rz);
            float dist = rn + 1e-6f;
            float na = fmaxf(rn, 1e-6f);
            float nb = fmaxf(sqrtf(vx * vx + vy * vy + vz * vz), 1e-6f);
            float dir_score = (rx * vx + ry * vy + rz * vz) / (na * nb);

            float a0 = 1.0f / dist;
            float a1 = dir_score;
            float a2 = dn;

            float h[32];
#pragma unroll
            for (int j = 0; j < 32; j++) {
                float s = fmaf(a2, sW1[j * 3 + 2],
                         fmaf(a1, sW1[j * 3 + 1],
                         fmaf(a0, sW1[j * 3 + 0], sb1[j])));
                h[j] = fmaxf(s, 0.0f);
            }

            const float4* w2v = reinterpret_cast<const float4*>(sW2);
            float s3 = sb3;
#pragma unroll
            for (int j = 0; j < 32; j++) {
                float s = sb2[j];
#pragma unroll
                for (int k4 = 0; k4 < 8; k4++) {
                    float4 w = w2v[j * 8 + k4];
                    s = fmaf(h[k4 * 4 + 0], w.x, s);
                    s = fmaf(h[k4 * 4 + 1], w.y, s);
                    s = fmaf(h[k4 * 4 + 2], w.z, s);
                    s = fmaf(h[k4 * 4 + 3], w.w, s);
                }
                s3 = fmaf(fmaxf(s, 0.0f), sW3[j], s3);
            }
            float sig = 1.0f / (1.0f + __expf(-s3));
            g_score_h[base + t] = __float2half(sig);
        }
        __syncthreads();
    }

    // ---- Grid barrier (sense-reversing; deadlock-free, replay-safe) ----
    __threadfence();                       // publish this block's scores
    __syncthreads();
    if (t == 0) {
        int gen = *(volatile int*)&g_gen;
        if (atomicAdd(&g_count, 1) == NB - 1) {
            g_count = 0;                   // reset BEFORE gen flip: no race
            __threadfence();
            atomicExch(&g_gen, gen + 1);   // release all spinners
        } else {
            while (*(volatile int*)&g_gen == gen) __nanosleep(32);
        }
    }
    __syncthreads();
    __threadfence();                       // acquire other blocks' scores

    // ---- Phase 2: gather (warp-specialized prologue overlap) ----
    int n4 = n_edges >> 2;
    int pre = n4 >> 3;                     // first eighth: L2-direct
    const int4* tv = reinterpret_cast<const int4*>(tgt);
    float4* ov = reinterpret_cast<float4*>(out);

    if (t < 256) {
        // Warps 0-7: copy the fp16 table into SMEM (uint4 = 8 halves).
        int n8 = (n_nodes + 7) >> 3;
        const uint4* src = reinterpret_cast<const uint4*>(g_score_h);
        uint4* dst = reinterpret_cast<uint4*>(stab);
        for (int k = t; k < n8; k += 256) dst[k] = src[k];
    } else {
        // Warps 8-31: gather the PRE range straight from L2.
        int tp = t - 256;
        int stride_pre = NB * 768;
        for (int j = blockIdx.x * 768 + tp; j < pre; j += stride_pre) {
            int4 a = tv[j];
            float4 o;
            o.x = __half2float(__ldg(&g_score_h[a.x]));
            o.y = __half2float(__ldg(&g_score_h[a.y]));
            o.z = __half2float(__ldg(&g_score_h[a.z]));
            o.w = __half2float(__ldg(&g_score_h[a.w]));
            ov[j] = o;
        }
    }
    __syncthreads();

    // All warps: remaining edge groups from the SMEM table.
    int stride = NB * NT;
    for (int j = pre + blockIdx.x * NT + t; j < n4; j += stride) {
        int4 a = tv[j];
        float4 o;
        o.x = __half2float(stab[a.x]);
        o.y = __half2float(stab[a.y]);
        o.z = __half2float(stab[a.z]);
        o.w = __half2float(stab[a.w]);
        ov[j] = o;
    }

    // Tail (n_edges % 4).
    if (blockIdx.x == 0 && t == 0) {
        for (int e = n4 << 2; e < n_edges; e++)
            out[e] = __half2float(stab[tgt[e]]);
    }
}

extern "C" void kernel_launch(void* const* d_in, const int* in_sizes, int n_in,
                              void* d_out, int out_size) {
    const float* x_t    = (const float*)d_in[0];
    const float* x_t_dt = (const float*)d_in[1];
    const int*   edge_index = (const int*)d_in[2];   // int32 (JAX x64 off)
    const float* W1 = (const float*)d_in[3];
    const float* b1 = (const float*)d_in[4];
    const float* W2 = (const float*)d_in[5];
    const float* b2 = (const float*)d_in[6];
    const float* W3 = (const float*)d_in[7];
    const float* b3 = (const float*)d_in[8];
    float* out = (float*)d_out;

    int n_nodes = in_sizes[0] / 7;
    int n_edges = in_sizes[2] / 2;
    const int* tgt = edge_index + n_edges;  // row 1 of (2, E)

    // Dynamic SMEM = max(fp16 table, phase-1 staging).
    size_t table_b = ((size_t)(n_nodes + 7) & ~7ull) * sizeof(__half);
    size_t stage_b = (size_t)NT * 7 * 2 * sizeof(float);
    size_t smem = (table_b > stage_b ? table_b : stage_b) + 16;

    cudaFuncSetAttribute(fused_kernel,
                         cudaFuncAttributeMaxDynamicSharedMemorySize,
                         (int)smem);
    fused_kernel<<<NB, NT, smem>>>(x_t, x_t_dt, W1, b1, W2, b2, W3, b3,
                                   tgt, out, n_nodes, n_edges);
}